// round 14
// baseline (speedup 1.0000x reference)
#include <cuda_runtime.h>
#include <cstdint>
#include <cuda_fp16.h>
#include <mma.h>

using namespace nvcuda;

#define DIM   1024
#define BATCH 8
#define SEQ   2048
#define MTOT  (BATCH*SEQ)   // 16384

// ---- fp16 GEMM (scores, PV) ----
#define BM 128
#define BN 128
#define BKH 64
#define KP  72
#define SC_LD 132
#define STAGE_HALVES (2*BM*KP)
#define SMEM_BYTES (2*STAGE_HALVES*2)  // 73728
#define NTH 128
#define NTRI 136                        // 16*17/2 lower-triangular tiles

// ---- projection GEMM: 256x128 CTA tile, 8 warps of 64x64 ----
#define PKP 40
#define PA_ST (256*PKP)                 // A stage halves (10240)
#define PB_ST (128*PKP)                 // B stage halves (5120)
#define PSMEM_BYTES ((2*PA_ST + 2*PB_ST)*2)   // 61440

// ---------------- scratch ----------------
__device__ __half g_hP[(size_t)BATCH * SEQ * SEQ];   // unnormalized exp(scores) fp16
__device__ float  g_RS[(size_t)MTOT];                // row sums
__device__ __half g_hQ [(size_t)MTOT * DIM];
__device__ __half g_hK [(size_t)MTOT * DIM];
__device__ __half g_hVt[(size_t)DIM * MTOT];
__device__ __half g_hWq[(size_t)DIM * DIM];
__device__ __half g_hWk[(size_t)DIM * DIM];
__device__ __half g_hWv[(size_t)DIM * DIM];
__device__ float  g_bias[2 * DIM];

__device__ __forceinline__ void cpa16(unsigned saddr, const void* gaddr) {
    asm volatile("cp.async.cg.shared.global [%0], [%1], 16;" :: "r"(saddr), "l"(gaddr));
}

// ---------------- projection GEMM core (256x128, 8 warps x 64x64) ----------------
// C(M,N) = A(M,K)*B(N,K)^T + bias; A fp32 (converted in-kernel), B fp16, C fp16.
template<bool TRANS_OUT>
__device__ __forceinline__
void ptg_core(const float* __restrict__ A, const __half* __restrict__ Bm,
              const float* __restrict__ bias, __half* __restrict__ C, int ldc,
              int m0, int n0, __half* sm)
{
    const int tid = threadIdx.x, warp = tid >> 5, lane = tid & 31;
    const int wm = warp >> 1, wn = warp & 1;   // 4x2 grid of 64x64 warp tiles
    const unsigned smBase = (unsigned)__cvta_generic_to_shared(sm);

    const int arr = tid >> 3;          // 0..31
    const int ac4 = (tid & 7) << 2;    // 0,4,..,28

    float4 areg[8];
    auto ldgA = [&](int k0) {
        #pragma unroll
        for (int i = 0; i < 8; i++)
            areg[i] = *reinterpret_cast<const float4*>(
                A + (size_t)(m0 + i * 32 + arr) * DIM + k0 + ac4);
    };
    auto stsA = [&](int st) {
        __half* dst0 = sm + st * PA_ST;
        #pragma unroll
        for (int i = 0; i < 8; i++) {
            __half2 h01 = __floats2half2_rn(areg[i].x, areg[i].y);
            __half2 h23 = __floats2half2_rn(areg[i].z, areg[i].w);
            uint2 u;
            u.x = *reinterpret_cast<unsigned*>(&h01);
            u.y = *reinterpret_cast<unsigned*>(&h23);
            *reinterpret_cast<uint2*>(dst0 + (i * 32 + arr) * PKP + ac4) = u;
        }
    };
    auto ldB = [&](int st, int k0) {
        const unsigned dB = smBase + (unsigned)(2 * PA_ST + st * PB_ST) * 2u;
        #pragma unroll
        for (int i = 0; i < 2; i++) {
            const int r = i * 64 + (tid >> 2), c8 = (tid & 3) << 3;
            cpa16(dB + (unsigned)(r * PKP + c8) * 2u,
                  Bm + (size_t)(n0 + r) * DIM + k0 + c8);
        }
        asm volatile("cp.async.commit_group;");
    };

    wmma::fragment<wmma::accumulator, 16, 16, 16, float> acc[4][4];
    #pragma unroll
    for (int i = 0; i < 4; i++)
        #pragma unroll
        for (int j = 0; j < 4; j++)
            wmma::fill_fragment(acc[i][j], 0.0f);

    ldgA(0);
    ldB(0, 0);

    const int nk = DIM / 32;   // 32
    for (int kt = 0; kt < nk; kt++) {
        const int b = kt & 1;
        stsA(b);
        if (kt + 1 < nk) {
            ldgA((kt + 1) * 32);
            ldB(b ^ 1, (kt + 1) * 32);
            asm volatile("cp.async.wait_group 1;" ::: "memory");
        } else {
            asm volatile("cp.async.wait_group 0;" ::: "memory");
        }
        __syncthreads();

        const __half* a0 = sm + b * PA_ST;
        const __half* b0 = sm + 2 * PA_ST + b * PB_ST;
        #pragma unroll
        for (int kk = 0; kk < 32; kk += 16) {
            wmma::fragment<wmma::matrix_a, 16, 16, 16, __half, wmma::row_major> af[4];
            #pragma unroll
            for (int i = 0; i < 4; i++)
                wmma::load_matrix_sync(af[i], a0 + (wm * 64 + i * 16) * PKP + kk, PKP);
            #pragma unroll
            for (int j = 0; j < 4; j++) {
                wmma::fragment<wmma::matrix_b, 16, 16, 16, __half, wmma::col_major> bf;
                wmma::load_matrix_sync(bf, b0 + (wn * 64 + j * 16) * PKP + kk, PKP);
                #pragma unroll
                for (int i = 0; i < 4; i++)
                    wmma::mma_sync(acc[i][j], af[i], bf, acc[i][j]);
            }
        }
        __syncthreads();
    }

    // ---- epilogue: four 64-row passes through smem ----
    float* sC = reinterpret_cast<float*>(sm);
    #pragma unroll
    for (int pass = 0; pass < 4; pass++) {
        if (pass) __syncthreads();
        if (wm == pass) {
            #pragma unroll
            for (int i = 0; i < 4; i++)
                #pragma unroll
                for (int j = 0; j < 4; j++)
                    wmma::store_matrix_sync(sC + (i * 16) * SC_LD + wn * 64 + j * 16,
                                            acc[i][j], SC_LD, wmma::mem_row_major);
        }
        __syncthreads();

        if (TRANS_OUT) {
            // 8 warps x 16 cols; lanes walk m (coalesced)
            #pragma unroll
            for (int cc = 0; cc < 16; cc++) {
                const int c = warp * 16 + cc;
                const float bb = __ldg(bias + n0 + c);
                #pragma unroll
                for (int r0 = 0; r0 < 64; r0 += 32) {
                    float v = sC[(r0 + lane) * SC_LD + c] + bb;
                    C[(size_t)(n0 + c) * ldc + m0 + pass * 64 + r0 + lane] = __float2half(v);
                }
            }
        } else {
            const int r  = tid >> 5;            // 0..7
            const int c4 = (tid & 31) << 2;     // 0..124
            float4 bb = *reinterpret_cast<const float4*>(bias + n0 + c4);
            #pragma unroll
            for (int rr = 0; rr < 64; rr += 8) {
                const int row = r + rr;
                float4 v = *reinterpret_cast<float4*>(&sC[row * SC_LD + c4]);
                __half2 h0 = __floats2half2_rn(v.x + bb.x, v.y + bb.y);
                __half2 h1 = __floats2half2_rn(v.z + bb.z, v.w + bb.w);
                __half2* dst = reinterpret_cast<__half2*>(
                    C + (size_t)(m0 + pass * 64 + row) * ldc + n0 + c4);
                dst[0] = h0; dst[1] = h1;
            }
        }
    }
}

// merged Q+K projection
__global__ __launch_bounds__(256, 1)
void ptgQK(const float* __restrict__ Aq, const float* __restrict__ Ak,
           const __half* __restrict__ Wq, const __half* __restrict__ Wk,
           const float* __restrict__ bias01,
           __half* __restrict__ Cq, __half* __restrict__ Ck)
{
    extern __shared__ __half sm[];
    const int m0 = blockIdx.x * 256;
    const int n0 = blockIdx.y * 128;
    if (blockIdx.z == 0)
        ptg_core<false>(Aq, Wq, bias01,       Cq, DIM, m0, n0, sm);
    else
        ptg_core<false>(Ak, Wk, bias01 + DIM, Ck, DIM, m0, n0, sm);
}

// V projection (transposed output)
__global__ __launch_bounds__(256, 1)
void ptgV(const float* __restrict__ A, const __half* __restrict__ Bm,
          const float* __restrict__ bias, __half* __restrict__ C, int ldc)
{
    extern __shared__ __half sm[];
    ptg_core<true>(A, Bm, bias, C, ldc, blockIdx.x * 256, blockIdx.y * 128, sm);
}

// ---------------- fp16 GEMM (scores-exp, PV) ----------------
template<bool TRI, bool KCAUSAL>
__global__ __launch_bounds__(NTH)
void tg(const __half* __restrict__ A, const __half* __restrict__ Bm,
        void* __restrict__ Cv, const float* __restrict__ rowsum,
        int lda, int ldb, int ldc, int K,
        long strideA, long strideB, long strideC, float scale)
{
    extern __shared__ __half sm[];

    int m0, n0, bz;
    if (TRI) {
        const int r = blockIdx.x;
        int mt = (int)((sqrtf(8.0f * (float)r + 1.0f) - 1.0f) * 0.5f);
        while ((mt + 1) * (mt + 2) / 2 <= r) mt++;
        while (mt * (mt + 1) / 2 > r) mt--;
        const int nt = r - mt * (mt + 1) / 2;
        m0 = mt * BM;
        n0 = nt * BN;
        bz = blockIdx.z;
    } else if (KCAUSAL) {
        const int perM = gridDim.y * gridDim.z;
        const int rank = blockIdx.x + gridDim.x * (blockIdx.y + gridDim.y * blockIdx.z);
        const int mt   = (gridDim.x - 1) - (rank / perM);
        const int rr   = rank % perM;
        m0 = mt * BM;
        n0 = (rr % gridDim.y) * BN;
        bz = rr / gridDim.y;
    } else {
        m0 = blockIdx.x * BM;
        n0 = blockIdx.y * BN;
        bz = blockIdx.z;
    }

    const __half* Ab = A  + (size_t)bz * strideA;
    const __half* Bb = Bm + (size_t)bz * strideB;

    const int kEnd = KCAUSAL ? (m0 + BM) : K;
    const int nk   = kEnd / BKH;

    const int tid  = threadIdx.x;
    const int warp = tid >> 5;
    const int wm   = warp >> 1;
    const int wn   = warp & 1;

    const unsigned smBase = (unsigned)__cvta_generic_to_shared(sm);

    wmma::fragment<wmma::accumulator, 16, 16, 16, float> acc[4][4];
    #pragma unroll
    for (int i = 0; i < 4; i++)
        #pragma unroll
        for (int j = 0; j < 4; j++)
            wmma::fill_fragment(acc[i][j], 0.0f);

    auto loadStage = [&](int st, int k0) {
        const unsigned base = smBase + (unsigned)(st * STAGE_HALVES) * 2u;
        #pragma unroll
        for (int i = 0; i < 8; i++) {
            const int ci = i * NTH + tid;
            const int r = ci >> 3, c8 = (ci & 7) << 3;
            cpa16(base + (unsigned)(r * KP + c8) * 2u,
                  Ab + (size_t)(m0 + r) * lda + k0 + c8);
        }
        const unsigned baseB = base + (unsigned)(BM * KP) * 2u;
        #pragma unroll
        for (int i = 0; i < 8; i++) {
            const int ci = i * NTH + tid;
            const int r = ci >> 3, c8 = (ci & 7) << 3;
            cpa16(baseB + (unsigned)(r * KP + c8) * 2u,
                  Bb + (size_t)(n0 + r) * ldb + k0 + c8);
        }
        asm volatile("cp.async.commit_group;");
    };

    loadStage(0, 0);

    for (int kt = 0; kt < nk; kt++) {
        if (kt + 1 < nk) {
            loadStage((kt + 1) & 1, (kt + 1) * BKH);
            asm volatile("cp.async.wait_group 1;" ::: "memory");
        } else {
            asm volatile("cp.async.wait_group 0;" ::: "memory");
        }
        __syncthreads();

        const __half* a0 = sm + (kt & 1) * STAGE_HALVES;
        const __half* b0 = a0 + BM * KP;

        #pragma unroll
        for (int kk = 0; kk < BKH; kk += 16) {
            wmma::fragment<wmma::matrix_a, 16, 16, 16, __half, wmma::row_major> af[4];
            #pragma unroll
            for (int i = 0; i < 4; i++)
                wmma::load_matrix_sync(af[i], a0 + (wm * 64 + i * 16) * KP + kk, KP);
            #pragma unroll
            for (int j = 0; j < 4; j++) {
                wmma::fragment<wmma::matrix_b, 16, 16, 16, __half, wmma::col_major> bf;
                wmma::load_matrix_sync(bf, b0 + (wn * 64 + j * 16) * KP + kk, KP);
                #pragma unroll
                for (int i = 0; i < 4; i++)
                    wmma::mma_sync(acc[i][j], af[i], bf, acc[i][j]);
            }
        }
        __syncthreads();
    }

    float* sC = reinterpret_cast<float*>(sm);
    #pragma unroll
    for (int i = 0; i < 4; i++)
        #pragma unroll
        for (int j = 0; j < 4; j++)
            wmma::store_matrix_sync(sC + (wm * 64 + i * 16) * SC_LD + wn * 64 + j * 16,
                                    acc[i][j], SC_LD, wmma::mem_row_major);
    __syncthreads();

    if (TRI) {
        __half* Cb = reinterpret_cast<__half*>(Cv) + (size_t)bz * strideC;
        const int r  = tid >> 5;
        const int c4 = (tid & 31) << 2;
        #pragma unroll
        for (int rr = 0; rr < BM; rr += 4) {
            const int m = m0 + r + rr;
            float4 v = *reinterpret_cast<float4*>(&sC[(r + rr) * SC_LD + c4]);
            const int n = n0 + c4;
            float e0 = (n + 0 <= m) ? __expf(v.x * scale) : 0.0f;
            float e1 = (n + 1 <= m) ? __expf(v.y * scale) : 0.0f;
            float e2 = (n + 2 <= m) ? __expf(v.z * scale) : 0.0f;
            float e3 = (n + 3 <= m) ? __expf(v.w * scale) : 0.0f;
            __half2 h0 = __floats2half2_rn(e0, e1);
            __half2 h1 = __floats2half2_rn(e2, e3);
            __half2* dst = reinterpret_cast<__half2*>(Cb + (size_t)m * ldc + n);
            dst[0] = h0; dst[1] = h1;
        }
    } else {
        const int r  = tid >> 5;
        const int c4 = (tid & 31) << 2;
        float* Cb = reinterpret_cast<float*>(Cv) + (size_t)bz * strideC;
        #pragma unroll
        for (int rr = 0; rr < BM; rr += 4) {
            const int m = m0 + r + rr;
            float4 v = *reinterpret_cast<float4*>(&sC[(r + rr) * SC_LD + c4]);
            float s = KCAUSAL ? (1.0f / __ldg(rowsum + (size_t)bz * SEQ + m)) : scale;
            v.x *= s; v.y *= s; v.z *= s; v.w *= s;
            *reinterpret_cast<float4*>(Cb + (size_t)m * ldc + n0 + c4) = v;
        }
    }
}

// ---------------- row sums of unnormalized probs ----------------
__global__ __launch_bounds__(256)
void rowsum_k(const __half* __restrict__ P, float* __restrict__ RS)
{
    __shared__ float red[8];
    const int row = blockIdx.x;
    const int b   = row >> 11;
    const int i   = row & (SEQ - 1);
    const __half2* p = reinterpret_cast<const __half2*>(P + ((size_t)b * SEQ + i) * SEQ);
    const int len2 = (((i >> 7) + 1) << 7) >> 1;
    const int tid = threadIdx.x, lane = tid & 31, w = tid >> 5;

    float s = 0.f;
    for (int j = tid; j < len2; j += 256) {
        float2 v = __half22float2(p[j]);
        s += v.x + v.y;
    }
    #pragma unroll
    for (int o = 16; o; o >>= 1) s += __shfl_xor_sync(0xffffffffu, s, o);
    if (lane == 0) red[w] = s;
    __syncthreads();
    if (tid == 0) {
        float ss = 0.f;
        #pragma unroll
        for (int x = 0; x < 8; x++) ss += red[x];
        RS[row] = ss;
    }
}

// ---------------- fp32 -> fp16 convert (weights only) ----------------
__global__ __launch_bounds__(256)
void f2h(const float* __restrict__ in, __half* __restrict__ out, int n4)
{
    int i = blockIdx.x * 256 + threadIdx.x;
    if (i < n4) {
        float4 v = reinterpret_cast<const float4*>(in)[i];
        __half2 h0 = __floats2half2_rn(v.x, v.y);
        __half2 h1 = __floats2half2_rn(v.z, v.w);
        reinterpret_cast<__half2*>(out)[2 * i + 0] = h0;
        reinterpret_cast<__half2*>(out)[2 * i + 1] = h1;
    }
}

// bout[e] = b[e] + dot(W[e,:], ctx)
__global__ __launch_bounds__(256)
void bias_prep(const float* __restrict__ W, const float* __restrict__ b,
               const float* __restrict__ ctx, float* __restrict__ bout)
{
    __shared__ float red[8];
    const int e = blockIdx.x;
    const int tid = threadIdx.x, lane = tid & 31, w = tid >> 5;
    float s = 0.f;
    for (int d = tid; d < DIM; d += 256) s += W[(size_t)e * DIM + d] * ctx[d];
    #pragma unroll
    for (int o = 16; o; o >>= 1) s += __shfl_xor_sync(0xffffffffu, s, o);
    if (lane == 0) red[w] = s;
    __syncthreads();
    if (tid == 0) {
        float t = 0.f;
        #pragma unroll
        for (int x = 0; x < 8; x++) t += red[x];
        bout[e] = b[e] + t;
    }
}

extern "C" void kernel_launch(void* const* d_in, const int* in_sizes, int n_in,
                              void* d_out, int out_size)
{
    const float* query = (const float*)d_in[0];
    const float* key   = (const float*)d_in[1];
    const float* value = (const float*)d_in[2];
    const float* ctx   = (const float*)d_in[3];
    const float* Wq    = (const float*)d_in[4];
    const float* bq    = (const float*)d_in[5];
    const float* Wk    = (const float*)d_in[6];
    const float* bk    = (const float*)d_in[7];
    const float* Wv    = (const float*)d_in[8];
    const float* bv    = (const float*)d_in[9];
    float* out = (float*)d_out;

    float *pRS, *pBias;
    __half *phP, *phQ, *phK, *phVt, *phWq, *phWk, *phWv;
    cudaGetSymbolAddress((void**)&pRS,  g_RS);
    cudaGetSymbolAddress((void**)&phP,  g_hP);
    cudaGetSymbolAddress((void**)&phQ,  g_hQ);
    cudaGetSymbolAddress((void**)&phK,  g_hK);
    cudaGetSymbolAddress((void**)&phVt, g_hVt);
    cudaGetSymbolAddress((void**)&phWq, g_hWq);
    cudaGetSymbolAddress((void**)&phWk, g_hWk);
    cudaGetSymbolAddress((void**)&phWv, g_hWv);
    cudaGetSymbolAddress((void**)&pBias, g_bias);

    cudaFuncSetAttribute(tg<true,  false>, cudaFuncAttributeMaxDynamicSharedMemorySize, SMEM_BYTES);
    cudaFuncSetAttribute(tg<false, true >, cudaFuncAttributeMaxDynamicSharedMemorySize, SMEM_BYTES);
    cudaFuncSetAttribute(ptgQK, cudaFuncAttributeMaxDynamicSharedMemorySize, PSMEM_BYTES);
    cudaFuncSetAttribute(ptgV,  cudaFuncAttributeMaxDynamicSharedMemorySize, PSMEM_BYTES);

    const int nW4 = DIM * DIM / 4;

    // ---- fork aux stream (V overlaps scores+rowsum) ----
    cudaStream_t s1 = 0;
    cudaEvent_t evFork = 0, evQK = 0, evJoin = 0;
    bool forked = false;
    if (cudaStreamCreateWithFlags(&s1, cudaStreamNonBlocking) == cudaSuccess) {
        cudaEventCreateWithFlags(&evFork, cudaEventDisableTiming);
        cudaEventCreateWithFlags(&evQK,   cudaEventDisableTiming);
        cudaEventCreateWithFlags(&evJoin, cudaEventDisableTiming);
        forked = (cudaEventRecord(evFork, 0) == cudaSuccess) &&
                 (cudaStreamWaitEvent(s1, evFork, 0) == cudaSuccess);
    }
    cudaStream_t sAux = forked ? s1 : 0;

    bias_prep<<<DIM, 256>>>(Wq, bq, ctx, pBias);
    bias_prep<<<DIM, 256>>>(Wk, bk, ctx, pBias + DIM);
    f2h<<<nW4 / 256, 256>>>(Wq, phWq, nW4);
    f2h<<<nW4 / 256, 256>>>(Wk, phWk, nW4);
    f2h<<<nW4 / 256, 256, 0, sAux>>>(Wv, phWv, nW4);

    // merged Q+K projection: 256x128 tiles
    dim3 gp2(MTOT / 256, DIM / 128, 2);
    ptgQK<<<gp2, 256, PSMEM_BYTES>>>(query, key, phWq, phWk, pBias, phQ, phK);

    if (forked) { cudaEventRecord(evQK, 0); cudaStreamWaitEvent(sAux, evQK, 0); }
    // V projection (aux) -> transposed fp16 Vt, overlaps scores+rowsum
    dim3 gpv(MTOT / 256, DIM / 128, 1);
    ptgV<<<gpv, 256, PSMEM_BYTES, sAux>>>(value, phWv, bv, phVt, MTOT);
    if (forked) cudaEventRecord(evJoin, sAux);

    // P' = exp(Q@K^T * scale) fp16, causal-masked — triangular grid
    dim3 gs(NTRI, 1, BATCH);
    tg<true, false><<<gs, NTH, SMEM_BYTES>>>(phQ, phK, phP, nullptr,
        DIM, DIM, SEQ, DIM,
        (long)SEQ * DIM, (long)SEQ * DIM, (long)SEQ * SEQ, 0.03125f);

    // row sums of P'
    rowsum_k<<<MTOT, 256>>>(phP, pRS);

    if (forked) cudaStreamWaitEvent(0, evJoin, 0);

    // out = (P' @ Vt^T) / rowsum  (K limited by causality; LPT remap)
    dim3 gv(SEQ / 128, DIM / 128, BATCH);
    tg<false, true><<<gv, NTH, SMEM_BYTES>>>(phP, phVt, out, pRS,
        SEQ, MTOT, DIM, SEQ,
        (long)SEQ * SEQ, (long)SEQ, (long)SEQ * DIM, 1.0f);

    if (forked) {
        cudaEventDestroy(evFork);
        cudaEventDestroy(evQK);
        cudaEventDestroy(evJoin);
    }
    if (s1) cudaStreamDestroy(s1);
}

// round 15
// speedup vs baseline: 1.0326x; 1.0326x over previous
#include <cuda_runtime.h>
#include <cstdint>
#include <cuda_fp16.h>
#include <mma.h>

using namespace nvcuda;

#define DIM   1024
#define BATCH 8
#define SEQ   2048
#define MTOT  (BATCH*SEQ)   // 16384

// ---- fp16 GEMM (scores, PV) ----
#define BM 128
#define BN 128
#define BKH 64
#define KP  72
#define SC_LD 132
#define STAGE_HALVES (2*BM*KP)
#define SMEM_BYTES (2*STAGE_HALVES*2)  // 73728
#define NTH 128
#define NTRI 136                        // 16*17/2 lower-triangular tiles

// ---- projection GEMM (fp32 A inline-converted), R12 config ----
#define PKP 40
#define PST 5120
#define PSMEM_BYTES (4*PST*2)           // 40960

// ---------------- scratch ----------------
__device__ __half g_hP[(size_t)BATCH * SEQ * SEQ];   // unnormalized exp(scores) fp16
__device__ float  g_RS[(size_t)MTOT];                // row sums
__device__ __half g_hQ [(size_t)MTOT * DIM];
__device__ __half g_hK [(size_t)MTOT * DIM];
__device__ __half g_hVt[(size_t)DIM * MTOT];
__device__ __half g_hWq[(size_t)DIM * DIM];
__device__ __half g_hWk[(size_t)DIM * DIM];
__device__ __half g_hWv[(size_t)DIM * DIM];
__device__ float  g_bias[2 * DIM];

__device__ __forceinline__ void cpa16(unsigned saddr, const void* gaddr) {
    asm volatile("cp.async.cg.shared.global [%0], [%1], 16;" :: "r"(saddr), "l"(gaddr));
}

// ---------------- projection GEMM core (R12: 128x128, 8 warps of 32x64) ----------------
template<bool TRANS_OUT>
__device__ __forceinline__
void ptg_core(const float* __restrict__ A, const __half* __restrict__ Bm,
              const float* __restrict__ bias, __half* __restrict__ C, int ldc,
              int m0, int n0, __half* sm)
{
    const int tid = threadIdx.x, warp = tid >> 5, lane = tid & 31;
    const int wm = warp >> 1, wn = warp & 1;
    const unsigned smBase = (unsigned)__cvta_generic_to_shared(sm);

    const int arr = tid >> 3;
    const int ac4 = (tid & 7) << 2;

    float4 areg[4];
    auto ldgA = [&](int k0) {
        #pragma unroll
        for (int i = 0; i < 4; i++)
            areg[i] = *reinterpret_cast<const float4*>(
                A + (size_t)(m0 + i * 32 + arr) * DIM + k0 + ac4);
    };
    auto stsA = [&](int st) {
        __half* dst0 = sm + st * PST;
        #pragma unroll
        for (int i = 0; i < 4; i++) {
            __half2 h01 = __floats2half2_rn(areg[i].x, areg[i].y);
            __half2 h23 = __floats2half2_rn(areg[i].z, areg[i].w);
            uint2 u;
            u.x = *reinterpret_cast<unsigned*>(&h01);
            u.y = *reinterpret_cast<unsigned*>(&h23);
            *reinterpret_cast<uint2*>(dst0 + (i * 32 + arr) * PKP + ac4) = u;
        }
    };
    auto ldB = [&](int st, int k0) {
        const unsigned dB = smBase + (unsigned)(2 * PST + st * PST) * 2u;
        #pragma unroll
        for (int i = 0; i < 2; i++) {
            const int r = i * 64 + (tid >> 2), c8 = (tid & 3) << 3;
            cpa16(dB + (unsigned)(r * PKP + c8) * 2u,
                  Bm + (size_t)(n0 + r) * DIM + k0 + c8);
        }
        asm volatile("cp.async.commit_group;");
    };

    wmma::fragment<wmma::accumulator, 16, 16, 16, float> acc[2][4];
    #pragma unroll
    for (int i = 0; i < 2; i++)
        #pragma unroll
        for (int j = 0; j < 4; j++)
            wmma::fill_fragment(acc[i][j], 0.0f);

    ldgA(0);
    ldB(0, 0);

    const int nk = DIM / 32;
    for (int kt = 0; kt < nk; kt++) {
        const int b = kt & 1;
        stsA(b);
        if (kt + 1 < nk) {
            ldgA((kt + 1) * 32);
            ldB(b ^ 1, (kt + 1) * 32);
            asm volatile("cp.async.wait_group 1;" ::: "memory");
        } else {
            asm volatile("cp.async.wait_group 0;" ::: "memory");
        }
        __syncthreads();

        const __half* a0 = sm + b * PST;
        const __half* b0 = sm + 2 * PST + b * PST;
        #pragma unroll
        for (int kk = 0; kk < 32; kk += 16) {
            wmma::fragment<wmma::matrix_a, 16, 16, 16, __half, wmma::row_major> af[2];
            #pragma unroll
            for (int i = 0; i < 2; i++)
                wmma::load_matrix_sync(af[i], a0 + (wm * 32 + i * 16) * PKP + kk, PKP);
            #pragma unroll
            for (int j = 0; j < 4; j++) {
                wmma::fragment<wmma::matrix_b, 16, 16, 16, __half, wmma::col_major> bf;
                wmma::load_matrix_sync(bf, b0 + (wn * 64 + j * 16) * PKP + kk, PKP);
                #pragma unroll
                for (int i = 0; i < 2; i++)
                    wmma::mma_sync(acc[i][j], af[i], bf, acc[i][j]);
            }
        }
        __syncthreads();
    }

    float* sC = reinterpret_cast<float*>(sm);
    #pragma unroll
    for (int pass = 0; pass < 2; pass++) {
        if (pass) __syncthreads();
        if ((wm >> 1) == pass) {
            #pragma unroll
            for (int i = 0; i < 2; i++)
                #pragma unroll
                for (int j = 0; j < 4; j++)
                    wmma::store_matrix_sync(sC + ((wm & 1) * 32 + i * 16) * SC_LD + wn * 64 + j * 16,
                                            acc[i][j], SC_LD, wmma::mem_row_major);
        }
        __syncthreads();

        if (TRANS_OUT) {
            #pragma unroll
            for (int cc = 0; cc < 16; cc++) {
                const int c = warp * 16 + cc;
                const float bb = __ldg(bias + n0 + c);
                #pragma unroll
                for (int r0 = 0; r0 < 64; r0 += 32) {
                    float v = sC[(r0 + lane) * SC_LD + c] + bb;
                    C[(size_t)(n0 + c) * ldc + m0 + pass * 64 + r0 + lane] = __float2half(v);
                }
            }
        } else {
            const int r  = tid >> 5;
            const int c4 = (tid & 31) << 2;
            float4 bb = *reinterpret_cast<const float4*>(bias + n0 + c4);
            #pragma unroll
            for (int rr = 0; rr < 64; rr += 8) {
                const int row = r + rr;
                float4 v = *reinterpret_cast<float4*>(&sC[row * SC_LD + c4]);
                __half2 h0 = __floats2half2_rn(v.x + bb.x, v.y + bb.y);
                __half2 h1 = __floats2half2_rn(v.z + bb.z, v.w + bb.w);
                __half2* dst = reinterpret_cast<__half2*>(
                    C + (size_t)(m0 + pass * 64 + row) * ldc + n0 + c4);
                dst[0] = h0; dst[1] = h1;
            }
        }
    }
}

// merged Q+K projection
__global__ __launch_bounds__(256, 2)
void ptgQK(const float* __restrict__ Aq, const float* __restrict__ Ak,
           const __half* __restrict__ Wq, const __half* __restrict__ Wk,
           const float* __restrict__ bias01,
           __half* __restrict__ Cq, __half* __restrict__ Ck)
{
    extern __shared__ __half sm[];
    const int m0 = blockIdx.x * 128;
    const int n0 = blockIdx.y * 128;
    if (blockIdx.z == 0)
        ptg_core<false>(Aq, Wq, bias01,       Cq, DIM, m0, n0, sm);
    else
        ptg_core<false>(Ak, Wk, bias01 + DIM, Ck, DIM, m0, n0, sm);
}

// V projection (transposed output)
__global__ __launch_bounds__(256, 2)
void ptgV(const float* __restrict__ A, const __half* __restrict__ Bm,
          const float* __restrict__ bias, __half* __restrict__ C, int ldc)
{
    extern __shared__ __half sm[];
    ptg_core<true>(A, Bm, bias, C, ldc, blockIdx.x * 128, blockIdx.y * 128, sm);
}

// ---------------- fp16 GEMM (scores-exp, PV) ----------------
template<bool TRI, bool KCAUSAL>
__global__ __launch_bounds__(NTH)
void tg(const __half* __restrict__ A, const __half* __restrict__ Bm,
        void* __restrict__ Cv, const float* __restrict__ rowsum,
        int lda, int ldb, int ldc, int K,
        long strideA, long strideB, long strideC, float scale)
{
    extern __shared__ __half sm[];

    int m0, n0, bz;
    if (TRI) {
        const int r = blockIdx.x;
        int mt = (int)((sqrtf(8.0f * (float)r + 1.0f) - 1.0f) * 0.5f);
        while ((mt + 1) * (mt + 2) / 2 <= r) mt++;
        while (mt * (mt + 1) / 2 > r) mt--;
        const int nt = r - mt * (mt + 1) / 2;
        m0 = mt * BM;
        n0 = nt * BN;
        bz = blockIdx.z;
    } else if (KCAUSAL) {
        const int perM = gridDim.y * gridDim.z;
        const int rank = blockIdx.x + gridDim.x * (blockIdx.y + gridDim.y * blockIdx.z);
        const int mt   = (gridDim.x - 1) - (rank / perM);
        const int rr   = rank % perM;
        m0 = mt * BM;
        n0 = (rr % gridDim.y) * BN;
        bz = rr / gridDim.y;
    } else {
        m0 = blockIdx.x * BM;
        n0 = blockIdx.y * BN;
        bz = blockIdx.z;
    }

    const __half* Ab = A  + (size_t)bz * strideA;
    const __half* Bb = Bm + (size_t)bz * strideB;

    const int kEnd = KCAUSAL ? (m0 + BM) : K;
    const int nk   = kEnd / BKH;

    const int tid  = threadIdx.x;
    const int warp = tid >> 5;
    const int wm   = warp >> 1;
    const int wn   = warp & 1;

    const unsigned smBase = (unsigned)__cvta_generic_to_shared(sm);

    wmma::fragment<wmma::accumulator, 16, 16, 16, float> acc[4][4];
    #pragma unroll
    for (int i = 0; i < 4; i++)
        #pragma unroll
        for (int j = 0; j < 4; j++)
            wmma::fill_fragment(acc[i][j], 0.0f);

    auto loadStage = [&](int st, int k0) {
        const unsigned base = smBase + (unsigned)(st * STAGE_HALVES) * 2u;
        #pragma unroll
        for (int i = 0; i < 8; i++) {
            const int ci = i * NTH + tid;
            const int r = ci >> 3, c8 = (ci & 7) << 3;
            cpa16(base + (unsigned)(r * KP + c8) * 2u,
                  Ab + (size_t)(m0 + r) * lda + k0 + c8);
        }
        const unsigned baseB = base + (unsigned)(BM * KP) * 2u;
        #pragma unroll
        for (int i = 0; i < 8; i++) {
            const int ci = i * NTH + tid;
            const int r = ci >> 3, c8 = (ci & 7) << 3;
            cpa16(baseB + (unsigned)(r * KP + c8) * 2u,
                  Bb + (size_t)(n0 + r) * ldb + k0 + c8);
        }
        asm volatile("cp.async.commit_group;");
    };

    loadStage(0, 0);

    for (int kt = 0; kt < nk; kt++) {
        if (kt + 1 < nk) {
            loadStage((kt + 1) & 1, (kt + 1) * BKH);
            asm volatile("cp.async.wait_group 1;" ::: "memory");
        } else {
            asm volatile("cp.async.wait_group 0;" ::: "memory");
        }
        __syncthreads();

        const __half* a0 = sm + (kt & 1) * STAGE_HALVES;
        const __half* b0 = a0 + BM * KP;

        #pragma unroll
        for (int kk = 0; kk < BKH; kk += 16) {
            wmma::fragment<wmma::matrix_a, 16, 16, 16, __half, wmma::row_major> af[4];
            #pragma unroll
            for (int i = 0; i < 4; i++)
                wmma::load_matrix_sync(af[i], a0 + (wm * 64 + i * 16) * KP + kk, KP);
            #pragma unroll
            for (int j = 0; j < 4; j++) {
                wmma::fragment<wmma::matrix_b, 16, 16, 16, __half, wmma::col_major> bf;
                wmma::load_matrix_sync(bf, b0 + (wn * 64 + j * 16) * KP + kk, KP);
                #pragma unroll
                for (int i = 0; i < 4; i++)
                    wmma::mma_sync(acc[i][j], af[i], bf, acc[i][j]);
            }
        }
        __syncthreads();
    }

    float* sC = reinterpret_cast<float*>(sm);
    #pragma unroll
    for (int i = 0; i < 4; i++)
        #pragma unroll
        for (int j = 0; j < 4; j++)
            wmma::store_matrix_sync(sC + (wm * 64 + i * 16) * SC_LD + wn * 64 + j * 16,
                                    acc[i][j], SC_LD, wmma::mem_row_major);
    __syncthreads();

    if (TRI) {
        __half* Cb = reinterpret_cast<__half*>(Cv) + (size_t)bz * strideC;
        const int r  = tid >> 5;
        const int c4 = (tid & 31) << 2;
        #pragma unroll
        for (int rr = 0; rr < BM; rr += 4) {
            const int m = m0 + r + rr;
            float4 v = *reinterpret_cast<float4*>(&sC[(r + rr) * SC_LD + c4]);
            const int n = n0 + c4;
            float e0 = (n + 0 <= m) ? __expf(v.x * scale) : 0.0f;
            float e1 = (n + 1 <= m) ? __expf(v.y * scale) : 0.0f;
            float e2 = (n + 2 <= m) ? __expf(v.z * scale) : 0.0f;
            float e3 = (n + 3 <= m) ? __expf(v.w * scale) : 0.0f;
            __half2 h0 = __floats2half2_rn(e0, e1);
            __half2 h1 = __floats2half2_rn(e2, e3);
            __half2* dst = reinterpret_cast<__half2*>(Cb + (size_t)m * ldc + n);
            dst[0] = h0; dst[1] = h1;
        }
    } else {
        const int r  = tid >> 5;
        const int c4 = (tid & 31) << 2;
        float* Cb = reinterpret_cast<float*>(Cv) + (size_t)bz * strideC;
        #pragma unroll
        for (int rr = 0; rr < BM; rr += 4) {
            const int m = m0 + r + rr;
            float4 v = *reinterpret_cast<float4*>(&sC[(r + rr) * SC_LD + c4]);
            float s = KCAUSAL ? (1.0f / __ldg(rowsum + (size_t)bz * SEQ + m)) : scale;
            v.x *= s; v.y *= s; v.z *= s; v.w *= s;
            *reinterpret_cast<float4*>(Cb + (size_t)m * ldc + n0 + c4) = v;
        }
    }
}

// ---------------- row sums of unnormalized probs ----------------
__global__ __launch_bounds__(256)
void rowsum_k(const __half* __restrict__ P, float* __restrict__ RS)
{
    __shared__ float red[8];
    const int row = blockIdx.x;
    const int b   = row >> 11;
    const int i   = row & (SEQ - 1);
    const __half2* p = reinterpret_cast<const __half2*>(P + ((size_t)b * SEQ + i) * SEQ);
    const int len2 = (((i >> 7) + 1) << 7) >> 1;
    const int tid = threadIdx.x, lane = tid & 31, w = tid >> 5;

    float s = 0.f;
    for (int j = tid; j < len2; j += 256) {
        float2 v = __half22float2(p[j]);
        s += v.x + v.y;
    }
    #pragma unroll
    for (int o = 16; o; o >>= 1) s += __shfl_xor_sync(0xffffffffu, s, o);
    if (lane == 0) red[w] = s;
    __syncthreads();
    if (tid == 0) {
        float ss = 0.f;
        #pragma unroll
        for (int x = 0; x < 8; x++) ss += red[x];
        RS[row] = ss;
    }
}

// ---------------- merged weight converts: z selects Wq/Wk/Wv ----------------
__global__ __launch_bounds__(256)
void f2h3(const float* __restrict__ w0, const float* __restrict__ w1,
          const float* __restrict__ w2,
          __half* __restrict__ o0, __half* __restrict__ o1, __half* __restrict__ o2)
{
    const float* in  = (blockIdx.z == 0) ? w0 : (blockIdx.z == 1) ? w1 : w2;
    __half*      out = (blockIdx.z == 0) ? o0 : (blockIdx.z == 1) ? o1 : o2;
    int i = blockIdx.x * 256 + threadIdx.x;
    float4 v = reinterpret_cast<const float4*>(in)[i];
    __half2 h0 = __floats2half2_rn(v.x, v.y);
    __half2 h1 = __floats2half2_rn(v.z, v.w);
    reinterpret_cast<__half2*>(out)[2 * i + 0] = h0;
    reinterpret_cast<__half2*>(out)[2 * i + 1] = h1;
}

// ---------------- merged bias prep: z selects (Wq,bq) / (Wk,bk) ----------------
__global__ __launch_bounds__(256)
void bias_prep2(const float* __restrict__ Wq, const float* __restrict__ bq,
                const float* __restrict__ Wk, const float* __restrict__ bk,
                const float* __restrict__ ctx, float* __restrict__ bout)
{
    __shared__ float red[8];
    const float* W = (blockIdx.z == 0) ? Wq : Wk;
    const float* b = (blockIdx.z == 0) ? bq : bk;
    float* out = bout + blockIdx.z * DIM;
    const int e = blockIdx.x;
    const int tid = threadIdx.x, lane = tid & 31, w = tid >> 5;
    float s = 0.f;
    for (int d = tid; d < DIM; d += 256) s += W[(size_t)e * DIM + d] * ctx[d];
    #pragma unroll
    for (int o = 16; o; o >>= 1) s += __shfl_xor_sync(0xffffffffu, s, o);
    if (lane == 0) red[w] = s;
    __syncthreads();
    if (tid == 0) {
        float t = 0.f;
        #pragma unroll
        for (int x = 0; x < 8; x++) t += red[x];
        out[e] = b[e] + t;
    }
}

extern "C" void kernel_launch(void* const* d_in, const int* in_sizes, int n_in,
                              void* d_out, int out_size)
{
    const float* query = (const float*)d_in[0];
    const float* key   = (const float*)d_in[1];
    const float* value = (const float*)d_in[2];
    const float* ctx   = (const float*)d_in[3];
    const float* Wq    = (const float*)d_in[4];
    const float* bq    = (const float*)d_in[5];
    const float* Wk    = (const float*)d_in[6];
    const float* bk    = (const float*)d_in[7];
    const float* Wv    = (const float*)d_in[8];
    const float* bv    = (const float*)d_in[9];
    float* out = (float*)d_out;

    float *pRS, *pBias;
    __half *phP, *phQ, *phK, *phVt, *phWq, *phWk, *phWv;
    cudaGetSymbolAddress((void**)&pRS,  g_RS);
    cudaGetSymbolAddress((void**)&phP,  g_hP);
    cudaGetSymbolAddress((void**)&phQ,  g_hQ);
    cudaGetSymbolAddress((void**)&phK,  g_hK);
    cudaGetSymbolAddress((void**)&phVt, g_hVt);
    cudaGetSymbolAddress((void**)&phWq, g_hWq);
    cudaGetSymbolAddress((void**)&phWk, g_hWk);
    cudaGetSymbolAddress((void**)&phWv, g_hWv);
    cudaGetSymbolAddress((void**)&pBias, g_bias);

    cudaFuncSetAttribute(tg<true,  false>, cudaFuncAttributeMaxDynamicSharedMemorySize, SMEM_BYTES);
    cudaFuncSetAttribute(tg<false, true >, cudaFuncAttributeMaxDynamicSharedMemorySize, SMEM_BYTES);

    const int nW4 = DIM * DIM / 4;

    // ---- fork aux stream (V projection overlaps scores+rowsum) ----
    cudaStream_t s1 = 0;
    cudaEvent_t evFork = 0, evQK = 0, evJoin = 0;
    bool forked = false;
    if (cudaStreamCreateWithFlags(&s1, cudaStreamNonBlocking) == cudaSuccess) {
        cudaEventCreateWithFlags(&evFork, cudaEventDisableTiming);
        cudaEventCreateWithFlags(&evQK,   cudaEventDisableTiming);
        cudaEventCreateWithFlags(&evJoin, cudaEventDisableTiming);
        forked = (cudaEventRecord(evFork, 0) == cudaSuccess) &&
                 (cudaStreamWaitEvent(s1, evFork, 0) == cudaSuccess);
    }
    cudaStream_t sAux = forked ? s1 : 0;

    // merged prelude
    bias_prep2<<<dim3(DIM, 1, 2), 256>>>(Wq, bq, Wk, bk, ctx, pBias);
    f2h3<<<dim3(nW4 / 256, 1, 3), 256>>>(Wq, Wk, Wv, phWq, phWk, phWv);

    // merged Q+K projection (R12 config: 128x128 tiles, 2 CTA/SM)
    dim3 gp2(MTOT / 128, DIM / 128, 2);
    ptgQK<<<gp2, 256, PSMEM_BYTES>>>(query, key, phWq, phWk, pBias, phQ, phK);

    if (forked) { cudaEventRecord(evQK, 0); cudaStreamWaitEvent(sAux, evQK, 0); }
    // V projection (aux) -> transposed fp16 Vt, overlaps scores+rowsum
    dim3 gpv(MTOT / 128, DIM / 128, 1);
    ptgV<<<gpv, 256, PSMEM_BYTES, sAux>>>(value, phWv, bv, phVt, MTOT);
    if (forked) cudaEventRecord(evJoin, sAux);

    // P' = exp(Q@K^T * scale) fp16, causal-masked — triangular grid
    dim3 gs(NTRI, 1, BATCH);
    tg<true, false><<<gs, NTH, SMEM_BYTES>>>(phQ, phK, phP, nullptr,
        DIM, DIM, SEQ, DIM,
        (long)SEQ * DIM, (long)SEQ * DIM, (long)SEQ * SEQ, 0.03125f);

    // row sums of P'
    rowsum_k<<<MTOT, 256>>>(phP, pRS);

    if (forked) cudaStreamWaitEvent(0, evJoin, 0);

    // out = (P' @ Vt^T) / rowsum  (K limited by causality; LPT remap)
    dim3 gv(SEQ / 128, DIM / 128, BATCH);
    tg<false, true><<<gv, NTH, SMEM_BYTES>>>(phP, phVt, out, pRS,
        SEQ, MTOT, DIM, SEQ,
        (long)SEQ * SEQ, (long)SEQ, (long)SEQ * DIM, 1.0f);

    if (forked) {
        cudaEventDestroy(evFork);
        cudaEventDestroy(evQK);
        cudaEventDestroy(evJoin);
    }
    if (s1) cudaStreamDestroy(s1);
}

// round 16
// speedup vs baseline: 1.0423x; 1.0094x over previous
#include <cuda_runtime.h>
#include <cstdint>
#include <cuda_fp16.h>
#include <mma.h>

using namespace nvcuda;

#define DIM   1024
#define BATCH 8
#define SEQ   2048
#define MTOT  (BATCH*SEQ)   // 16384

// ---- fp16 GEMM (scores, PV) ----
#define BM 128
#define BN 128
#define BKH 64
#define KP  72
#define SC_LD 132
#define STAGE_HALVES (2*BM*KP)
#define SMEM_BYTES (2*STAGE_HALVES*2)  // 73728
#define NTH 128
#define NTRI 136                        // 16*17/2 lower-triangular tiles

// ---- projection GEMM (fp32 A inline-converted) ----
#define PKP 40
#define PST 5120
#define PSMEM_BYTES (4*PST*2)           // 40960

// ---------------- scratch ----------------
__device__ __half g_hP[(size_t)BATCH * SEQ * SEQ];   // unnormalized exp(scores) fp16
__device__ float  g_RS[(size_t)MTOT];                // row sums
__device__ __half g_hQ [(size_t)MTOT * DIM];
__device__ __half g_hK [(size_t)MTOT * DIM];
__device__ __half g_hVt[(size_t)DIM * MTOT];
__device__ __half g_hWq[(size_t)DIM * DIM];
__device__ __half g_hWk[(size_t)DIM * DIM];
__device__ __half g_hWv[(size_t)DIM * DIM];
__device__ float  g_bias[2 * DIM];

__device__ __forceinline__ void cpa16(unsigned saddr, const void* gaddr) {
    asm volatile("cp.async.cg.shared.global [%0], [%1], 16;" :: "r"(saddr), "l"(gaddr));
}

// ---------------- projection GEMM core (128x128, 8 warps of 32x64, 2 CTA/SM) ----------------
template<bool TRANS_OUT>
__device__ __forceinline__
void ptg_core(const float* __restrict__ A, const __half* __restrict__ Bm,
              const float* __restrict__ bias, __half* __restrict__ C, int ldc,
              int m0, int n0, __half* sm)
{
    const int tid = threadIdx.x, warp = tid >> 5, lane = tid & 31;
    const int wm = warp >> 1, wn = warp & 1;
    const unsigned smBase = (unsigned)__cvta_generic_to_shared(sm);

    const int arr = tid >> 3;
    const int ac4 = (tid & 7) << 2;

    float4 areg[4];
    auto ldgA = [&](int k0) {
        #pragma unroll
        for (int i = 0; i < 4; i++)
            areg[i] = *reinterpret_cast<const float4*>(
                A + (size_t)(m0 + i * 32 + arr) * DIM + k0 + ac4);
    };
    auto stsA = [&](int st) {
        __half* dst0 = sm + st * PST;
        #pragma unroll
        for (int i = 0; i < 4; i++) {
            __half2 h01 = __floats2half2_rn(areg[i].x, areg[i].y);
            __half2 h23 = __floats2half2_rn(areg[i].z, areg[i].w);
            uint2 u;
            u.x = *reinterpret_cast<unsigned*>(&h01);
            u.y = *reinterpret_cast<unsigned*>(&h23);
            *reinterpret_cast<uint2*>(dst0 + (i * 32 + arr) * PKP + ac4) = u;
        }
    };
    auto ldB = [&](int st, int k0) {
        const unsigned dB = smBase + (unsigned)(2 * PST + st * PST) * 2u;
        #pragma unroll
        for (int i = 0; i < 2; i++) {
            const int r = i * 64 + (tid >> 2), c8 = (tid & 3) << 3;
            cpa16(dB + (unsigned)(r * PKP + c8) * 2u,
                  Bm + (size_t)(n0 + r) * DIM + k0 + c8);
        }
        asm volatile("cp.async.commit_group;");
    };

    wmma::fragment<wmma::accumulator, 16, 16, 16, float> acc[2][4];
    #pragma unroll
    for (int i = 0; i < 2; i++)
        #pragma unroll
        for (int j = 0; j < 4; j++)
            wmma::fill_fragment(acc[i][j], 0.0f);

    ldgA(0);
    ldB(0, 0);

    const int nk = DIM / 32;
    for (int kt = 0; kt < nk; kt++) {
        const int b = kt & 1;
        stsA(b);
        if (kt + 1 < nk) {
            ldgA((kt + 1) * 32);
            ldB(b ^ 1, (kt + 1) * 32);
            asm volatile("cp.async.wait_group 1;" ::: "memory");
        } else {
            asm volatile("cp.async.wait_group 0;" ::: "memory");
        }
        __syncthreads();

        const __half* a0 = sm + b * PST;
        const __half* b0 = sm + 2 * PST + b * PST;
        #pragma unroll
        for (int kk = 0; kk < 32; kk += 16) {
            wmma::fragment<wmma::matrix_a, 16, 16, 16, __half, wmma::row_major> af[2];
            #pragma unroll
            for (int i = 0; i < 2; i++)
                wmma::load_matrix_sync(af[i], a0 + (wm * 32 + i * 16) * PKP + kk, PKP);
            #pragma unroll
            for (int j = 0; j < 4; j++) {
                wmma::fragment<wmma::matrix_b, 16, 16, 16, __half, wmma::col_major> bf;
                wmma::load_matrix_sync(bf, b0 + (wn * 64 + j * 16) * PKP + kk, PKP);
                #pragma unroll
                for (int i = 0; i < 2; i++)
                    wmma::mma_sync(acc[i][j], af[i], bf, acc[i][j]);
            }
        }
        __syncthreads();
    }

    float* sC = reinterpret_cast<float*>(sm);
    #pragma unroll
    for (int pass = 0; pass < 2; pass++) {
        if (pass) __syncthreads();
        if ((wm >> 1) == pass) {
            #pragma unroll
            for (int i = 0; i < 2; i++)
                #pragma unroll
                for (int j = 0; j < 4; j++)
                    wmma::store_matrix_sync(sC + ((wm & 1) * 32 + i * 16) * SC_LD + wn * 64 + j * 16,
                                            acc[i][j], SC_LD, wmma::mem_row_major);
        }
        __syncthreads();

        if (TRANS_OUT) {
            #pragma unroll
            for (int cc = 0; cc < 16; cc++) {
                const int c = warp * 16 + cc;
                const float bb = __ldg(bias + n0 + c);
                #pragma unroll
                for (int r0 = 0; r0 < 64; r0 += 32) {
                    float v = sC[(r0 + lane) * SC_LD + c] + bb;
                    C[(size_t)(n0 + c) * ldc + m0 + pass * 64 + r0 + lane] = __float2half(v);
                }
            }
        } else {
            const int r  = tid >> 5;
            const int c4 = (tid & 31) << 2;
            float4 bb = *reinterpret_cast<const float4*>(bias + n0 + c4);
            #pragma unroll
            for (int rr = 0; rr < 64; rr += 8) {
                const int row = r + rr;
                float4 v = *reinterpret_cast<float4*>(&sC[row * SC_LD + c4]);
                __half2 h0 = __floats2half2_rn(v.x + bb.x, v.y + bb.y);
                __half2 h1 = __floats2half2_rn(v.z + bb.z, v.w + bb.w);
                __half2* dst = reinterpret_cast<__half2*>(
                    C + (size_t)(m0 + pass * 64 + row) * ldc + n0 + c4);
                dst[0] = h0; dst[1] = h1;
            }
        }
    }
}

// merged Q+K projection
__global__ __launch_bounds__(256, 2)
void ptgQK(const float* __restrict__ Aq, const float* __restrict__ Ak,
           const __half* __restrict__ Wq, const __half* __restrict__ Wk,
           const float* __restrict__ bias01,
           __half* __restrict__ Cq, __half* __restrict__ Ck)
{
    extern __shared__ __half sm[];
    const int m0 = blockIdx.x * 128;
    const int n0 = blockIdx.y * 128;
    if (blockIdx.z == 0)
        ptg_core<false>(Aq, Wq, bias01,       Cq, DIM, m0, n0, sm);
    else
        ptg_core<false>(Ak, Wk, bias01 + DIM, Ck, DIM, m0, n0, sm);
}

// V projection (transposed output)
__global__ __launch_bounds__(256, 2)
void ptgV(const float* __restrict__ A, const __half* __restrict__ Bm,
          const float* __restrict__ bias, __half* __restrict__ C, int ldc)
{
    extern __shared__ __half sm[];
    ptg_core<true>(A, Bm, bias, C, ldc, blockIdx.x * 128, blockIdx.y * 128, sm);
}

// ---------------- fp16 GEMM (scores-exp, PV) — now 3 CTA/SM ----------------
template<bool TRI, bool KCAUSAL>
__global__ __launch_bounds__(NTH, 3)
void tg(const __half* __restrict__ A, const __half* __restrict__ Bm,
        void* __restrict__ Cv, const float* __restrict__ rowsum,
        int lda, int ldb, int ldc, int K,
        long strideA, long strideB, long strideC, float scale)
{
    extern __shared__ __half sm[];

    int m0, n0, bz;
    if (TRI) {
        const int r = blockIdx.x;
        int mt = (int)((sqrtf(8.0f * (float)r + 1.0f) - 1.0f) * 0.5f);
        while ((mt + 1) * (mt + 2) / 2 <= r) mt++;
        while (mt * (mt + 1) / 2 > r) mt--;
        const int nt = r - mt * (mt + 1) / 2;
        m0 = mt * BM;
        n0 = nt * BN;
        bz = blockIdx.z;
    } else if (KCAUSAL) {
        const int perM = gridDim.y * gridDim.z;
        const int rank = blockIdx.x + gridDim.x * (blockIdx.y + gridDim.y * blockIdx.z);
        const int mt   = (gridDim.x - 1) - (rank / perM);
        const int rr   = rank % perM;
        m0 = mt * BM;
        n0 = (rr % gridDim.y) * BN;
        bz = rr / gridDim.y;
    } else {
        m0 = blockIdx.x * BM;
        n0 = blockIdx.y * BN;
        bz = blockIdx.z;
    }

    const __half* Ab = A  + (size_t)bz * strideA;
    const __half* Bb = Bm + (size_t)bz * strideB;

    const int kEnd = KCAUSAL ? (m0 + BM) : K;
    const int nk   = kEnd / BKH;

    const int tid  = threadIdx.x;
    const int warp = tid >> 5;
    const int wm   = warp >> 1;
    const int wn   = warp & 1;

    const unsigned smBase = (unsigned)__cvta_generic_to_shared(sm);

    wmma::fragment<wmma::accumulator, 16, 16, 16, float> acc[4][4];
    #pragma unroll
    for (int i = 0; i < 4; i++)
        #pragma unroll
        for (int j = 0; j < 4; j++)
            wmma::fill_fragment(acc[i][j], 0.0f);

    auto loadStage = [&](int st, int k0) {
        const unsigned base = smBase + (unsigned)(st * STAGE_HALVES) * 2u;
        #pragma unroll
        for (int i = 0; i < 8; i++) {
            const int ci = i * NTH + tid;
            const int r = ci >> 3, c8 = (ci & 7) << 3;
            cpa16(base + (unsigned)(r * KP + c8) * 2u,
                  Ab + (size_t)(m0 + r) * lda + k0 + c8);
        }
        const unsigned baseB = base + (unsigned)(BM * KP) * 2u;
        #pragma unroll
        for (int i = 0; i < 8; i++) {
            const int ci = i * NTH + tid;
            const int r = ci >> 3, c8 = (ci & 7) << 3;
            cpa16(baseB + (unsigned)(r * KP + c8) * 2u,
                  Bb + (size_t)(n0 + r) * ldb + k0 + c8);
        }
        asm volatile("cp.async.commit_group;");
    };

    loadStage(0, 0);

    for (int kt = 0; kt < nk; kt++) {
        if (kt + 1 < nk) {
            loadStage((kt + 1) & 1, (kt + 1) * BKH);
            asm volatile("cp.async.wait_group 1;" ::: "memory");
        } else {
            asm volatile("cp.async.wait_group 0;" ::: "memory");
        }
        __syncthreads();

        const __half* a0 = sm + (kt & 1) * STAGE_HALVES;
        const __half* b0 = a0 + BM * KP;

        #pragma unroll
        for (int kk = 0; kk < BKH; kk += 16) {
            wmma::fragment<wmma::matrix_a, 16, 16, 16, __half, wmma::row_major> af[4];
            #pragma unroll
            for (int i = 0; i < 4; i++)
                wmma::load_matrix_sync(af[i], a0 + (wm * 64 + i * 16) * KP + kk, KP);
            #pragma unroll
            for (int j = 0; j < 4; j++) {
                wmma::fragment<wmma::matrix_b, 16, 16, 16, __half, wmma::col_major> bf;
                wmma::load_matrix_sync(bf, b0 + (wn * 64 + j * 16) * KP + kk, KP);
                #pragma unroll
                for (int i = 0; i < 4; i++)
                    wmma::mma_sync(acc[i][j], af[i], bf, acc[i][j]);
            }
        }
        __syncthreads();
    }

    float* sC = reinterpret_cast<float*>(sm);
    #pragma unroll
    for (int i = 0; i < 4; i++)
        #pragma unroll
        for (int j = 0; j < 4; j++)
            wmma::store_matrix_sync(sC + (wm * 64 + i * 16) * SC_LD + wn * 64 + j * 16,
                                    acc[i][j], SC_LD, wmma::mem_row_major);
    __syncthreads();

    if (TRI) {
        __half* Cb = reinterpret_cast<__half*>(Cv) + (size_t)bz * strideC;
        const int r  = tid >> 5;
        const int c4 = (tid & 31) << 2;
        #pragma unroll
        for (int rr = 0; rr < BM; rr += 4) {
            const int m = m0 + r + rr;
            float4 v = *reinterpret_cast<float4*>(&sC[(r + rr) * SC_LD + c4]);
            const int n = n0 + c4;
            float e0 = (n + 0 <= m) ? __expf(v.x * scale) : 0.0f;
            float e1 = (n + 1 <= m) ? __expf(v.y * scale) : 0.0f;
            float e2 = (n + 2 <= m) ? __expf(v.z * scale) : 0.0f;
            float e3 = (n + 3 <= m) ? __expf(v.w * scale) : 0.0f;
            __half2 h0 = __floats2half2_rn(e0, e1);
            __half2 h1 = __floats2half2_rn(e2, e3);
            __half2* dst = reinterpret_cast<__half2*>(Cb + (size_t)m * ldc + n);
            dst[0] = h0; dst[1] = h1;
        }
    } else {
        const int r  = tid >> 5;
        const int c4 = (tid & 31) << 2;
        float* Cb = reinterpret_cast<float*>(Cv) + (size_t)bz * strideC;
        #pragma unroll
        for (int rr = 0; rr < BM; rr += 4) {
            const int m = m0 + r + rr;
            float4 v = *reinterpret_cast<float4*>(&sC[(r + rr) * SC_LD + c4]);
            float s = KCAUSAL ? (1.0f / __ldg(rowsum + (size_t)bz * SEQ + m)) : scale;
            v.x *= s; v.y *= s; v.z *= s; v.w *= s;
            *reinterpret_cast<float4*>(Cb + (size_t)m * ldc + n0 + c4) = v;
        }
    }
}

// ---------------- row sums of unnormalized probs ----------------
__global__ __launch_bounds__(256)
void rowsum_k(const __half* __restrict__ P, float* __restrict__ RS)
{
    __shared__ float red[8];
    const int row = blockIdx.x;
    const int b   = row >> 11;
    const int i   = row & (SEQ - 1);
    const __half2* p = reinterpret_cast<const __half2*>(P + ((size_t)b * SEQ + i) * SEQ);
    const int len2 = (((i >> 7) + 1) << 7) >> 1;
    const int tid = threadIdx.x, lane = tid & 31, w = tid >> 5;

    float s = 0.f;
    for (int j = tid; j < len2; j += 256) {
        float2 v = __half22float2(p[j]);
        s += v.x + v.y;
    }
    #pragma unroll
    for (int o = 16; o; o >>= 1) s += __shfl_xor_sync(0xffffffffu, s, o);
    if (lane == 0) red[w] = s;
    __syncthreads();
    if (tid == 0) {
        float ss = 0.f;
        #pragma unroll
        for (int x = 0; x < 8; x++) ss += red[x];
        RS[row] = ss;
    }
}

// ---------------- fp32 -> fp16 convert (weights only) ----------------
__global__ __launch_bounds__(256)
void f2h(const float* __restrict__ in, __half* __restrict__ out, int n4)
{
    int i = blockIdx.x * 256 + threadIdx.x;
    if (i < n4) {
        float4 v = reinterpret_cast<const float4*>(in)[i];
        __half2 h0 = __floats2half2_rn(v.x, v.y);
        __half2 h1 = __floats2half2_rn(v.z, v.w);
        reinterpret_cast<__half2*>(out)[2 * i + 0] = h0;
        reinterpret_cast<__half2*>(out)[2 * i + 1] = h1;
    }
}

// bout[e] = b[e] + dot(W[e,:], ctx)
__global__ __launch_bounds__(256)
void bias_prep(const float* __restrict__ W, const float* __restrict__ b,
               const float* __restrict__ ctx, float* __restrict__ bout)
{
    __shared__ float red[8];
    const int e = blockIdx.x;
    const int tid = threadIdx.x, lane = tid & 31, w = tid >> 5;
    float s = 0.f;
    for (int d = tid; d < DIM; d += 256) s += W[(size_t)e * DIM + d] * ctx[d];
    #pragma unroll
    for (int o = 16; o; o >>= 1) s += __shfl_xor_sync(0xffffffffu, s, o);
    if (lane == 0) red[w] = s;
    __syncthreads();
    if (tid == 0) {
        float t = 0.f;
        #pragma unroll
        for (int x = 0; x < 8; x++) t += red[x];
        bout[e] = b[e] + t;
    }
}

extern "C" void kernel_launch(void* const* d_in, const int* in_sizes, int n_in,
                              void* d_out, int out_size)
{
    const float* query = (const float*)d_in[0];
    const float* key   = (const float*)d_in[1];
    const float* value = (const float*)d_in[2];
    const float* ctx   = (const float*)d_in[3];
    const float* Wq    = (const float*)d_in[4];
    const float* bq    = (const float*)d_in[5];
    const float* Wk    = (const float*)d_in[6];
    const float* bk    = (const float*)d_in[7];
    const float* Wv    = (const float*)d_in[8];
    const float* bv    = (const float*)d_in[9];
    float* out = (float*)d_out;

    float *pRS, *pBias;
    __half *phP, *phQ, *phK, *phVt, *phWq, *phWk, *phWv;
    cudaGetSymbolAddress((void**)&pRS,  g_RS);
    cudaGetSymbolAddress((void**)&phP,  g_hP);
    cudaGetSymbolAddress((void**)&phQ,  g_hQ);
    cudaGetSymbolAddress((void**)&phK,  g_hK);
    cudaGetSymbolAddress((void**)&phVt, g_hVt);
    cudaGetSymbolAddress((void**)&phWq, g_hWq);
    cudaGetSymbolAddress((void**)&phWk, g_hWk);
    cudaGetSymbolAddress((void**)&phWv, g_hWv);
    cudaGetSymbolAddress((void**)&pBias, g_bias);

    cudaFuncSetAttribute(tg<true,  false>, cudaFuncAttributeMaxDynamicSharedMemorySize, SMEM_BYTES);
    cudaFuncSetAttribute(tg<false, true >, cudaFuncAttributeMaxDynamicSharedMemorySize, SMEM_BYTES);

    const int nW4 = DIM * DIM / 4;

    // ---- fork aux stream (V projection overlaps scores+rowsum) ----
    cudaStream_t s1 = 0;
    cudaEvent_t evFork = 0, evQK = 0, evJoin = 0;
    bool forked = false;
    if (cudaStreamCreateWithFlags(&s1, cudaStreamNonBlocking) == cudaSuccess) {
        cudaEventCreateWithFlags(&evFork, cudaEventDisableTiming);
        cudaEventCreateWithFlags(&evQK,   cudaEventDisableTiming);
        cudaEventCreateWithFlags(&evJoin, cudaEventDisableTiming);
        forked = (cudaEventRecord(evFork, 0) == cudaSuccess) &&
                 (cudaStreamWaitEvent(s1, evFork, 0) == cudaSuccess);
    }
    cudaStream_t sAux = forked ? s1 : 0;

    // prelude (R12 layout)
    bias_prep<<<DIM, 256>>>(Wq, bq, ctx, pBias);
    bias_prep<<<DIM, 256>>>(Wk, bk, ctx, pBias + DIM);
    f2h<<<nW4 / 256, 256>>>(Wq, phWq, nW4);
    f2h<<<nW4 / 256, 256>>>(Wk, phWk, nW4);
    f2h<<<nW4 / 256, 256, 0, sAux>>>(Wv, phWv, nW4);

    // merged Q+K projection
    dim3 gp2(MTOT / 128, DIM / 128, 2);
    ptgQK<<<gp2, 256, PSMEM_BYTES>>>(query, key, phWq, phWk, pBias, phQ, phK);

    if (forked) { cudaEventRecord(evQK, 0); cudaStreamWaitEvent(sAux, evQK, 0); }
    // V projection (aux) -> transposed fp16 Vt, overlaps scores+rowsum
    dim3 gpv(MTOT / 128, DIM / 128, 1);
    ptgV<<<gpv, 256, PSMEM_BYTES, sAux>>>(value, phWv, bv, phVt, MTOT);
    if (forked) cudaEventRecord(evJoin, sAux);

    // P' = exp(Q@K^T * scale) fp16, causal-masked — triangular grid
    dim3 gs(NTRI, 1, BATCH);
    tg<true, false><<<gs, NTH, SMEM_BYTES>>>(phQ, phK, phP, nullptr,
        DIM, DIM, SEQ, DIM,
        (long)SEQ * DIM, (long)SEQ * DIM, (long)SEQ * SEQ, 0.03125f);

    // row sums of P'
    rowsum_k<<<MTOT, 256>>>(phP, pRS);

    if (forked) cudaStreamWaitEvent(0, evJoin, 0);

    // out = (P' @ Vt^T) / rowsum  (K limited by causality; LPT remap)
    dim3 gv(SEQ / 128, DIM / 128, BATCH);
    tg<false, true><<<gv, NTH, SMEM_BYTES>>>(phP, phVt, out, pRS,
        SEQ, MTOT, DIM, SEQ,
        (long)SEQ * SEQ, (long)SEQ, (long)SEQ * DIM, 1.0f);

    if (forked) {
        cudaEventDestroy(evFork);
        cudaEventDestroy(evQK);
        cudaEventDestroy(evJoin);
    }
    if (s1) cudaStreamDestroy(s1);
}

// round 17
// speedup vs baseline: 1.1162x; 1.0709x over previous
#include <cuda_runtime.h>
#include <cstdint>
#include <cuda_fp16.h>
#include <mma.h>

using namespace nvcuda;

#define DIM   1024
#define BATCH 8
#define SEQ   2048
#define MTOT  (BATCH*SEQ)   // 16384

// ---- fp16 GEMM (scores, PV): 3-stage pipeline, 1 sync/chunk ----
#define BM 128
#define BN 128
#define BKH 64
#define KP  72
#define SC_LD 132
#define STAGE_HALVES (2*BM*KP)          // 18432 halves per stage (A+B)
#define SMEM_BYTES (3*STAGE_HALVES*2)   // 110592
#define NTH 128
#define NTRI 136

// ---- projection GEMM: 3-stage, 1 sync/chunk ----
#define PKP 40
#define PST 5120                         // halves per A/B stage tile
#define PSMEM_BYTES (6*PST*2)            // 61440

// ---------------- scratch ----------------
__device__ __half g_hP[(size_t)BATCH * SEQ * SEQ];   // unnormalized exp(scores) fp16
__device__ float  g_RS[(size_t)MTOT];                // row sums
__device__ __half g_hQ [(size_t)MTOT * DIM];
__device__ __half g_hK [(size_t)MTOT * DIM];
__device__ __half g_hVt[(size_t)DIM * MTOT];
__device__ __half g_hWq[(size_t)DIM * DIM];
__device__ __half g_hWk[(size_t)DIM * DIM];
__device__ __half g_hWv[(size_t)DIM * DIM];
__device__ float  g_bias[2 * DIM];

__device__ __forceinline__ void cpa16(unsigned saddr, const void* gaddr) {
    asm volatile("cp.async.cg.shared.global [%0], [%1], 16;" :: "r"(saddr), "l"(gaddr));
}

// ---------------- projection GEMM core (128x128, 8 warps of 32x64, 3-stage) ----------------
template<bool TRANS_OUT>
__device__ __forceinline__
void ptg_core(const float* __restrict__ A, const __half* __restrict__ Bm,
              const float* __restrict__ bias, __half* __restrict__ C, int ldc,
              int m0, int n0, __half* sm)
{
    const int tid = threadIdx.x, warp = tid >> 5, lane = tid & 31;
    const int wm = warp >> 1, wn = warp & 1;
    const unsigned smBase = (unsigned)__cvta_generic_to_shared(sm);

    const int arr = tid >> 3;
    const int ac4 = (tid & 7) << 2;

    float4 areg[4];
    auto ldgA = [&](int k0) {
        #pragma unroll
        for (int i = 0; i < 4; i++)
            areg[i] = *reinterpret_cast<const float4*>(
                A + (size_t)(m0 + i * 32 + arr) * DIM + k0 + ac4);
    };
    auto stsA = [&](int st) {
        __half* dst0 = sm + st * PST;
        #pragma unroll
        for (int i = 0; i < 4; i++) {
            __half2 h01 = __floats2half2_rn(areg[i].x, areg[i].y);
            __half2 h23 = __floats2half2_rn(areg[i].z, areg[i].w);
            uint2 u;
            u.x = *reinterpret_cast<unsigned*>(&h01);
            u.y = *reinterpret_cast<unsigned*>(&h23);
            *reinterpret_cast<uint2*>(dst0 + (i * 32 + arr) * PKP + ac4) = u;
        }
    };
    auto ldB = [&](int st, int k0) {
        const unsigned dB = smBase + (unsigned)(3 * PST + st * PST) * 2u;
        #pragma unroll
        for (int i = 0; i < 2; i++) {
            const int r = i * 64 + (tid >> 2), c8 = (tid & 3) << 3;
            cpa16(dB + (unsigned)(r * PKP + c8) * 2u,
                  Bm + (size_t)(n0 + r) * DIM + k0 + c8);
        }
        asm volatile("cp.async.commit_group;");
    };

    wmma::fragment<wmma::accumulator, 16, 16, 16, float> acc[2][4];
    #pragma unroll
    for (int i = 0; i < 2; i++)
        #pragma unroll
        for (int j = 0; j < 4; j++)
            wmma::fill_fragment(acc[i][j], 0.0f);

    const int nk = DIM / 32;   // 32
    ldB(0, 0);
    ldB(1, 32);
    ldgA(0);

    for (int kt = 0; kt < nk; kt++) {
        const int b = kt % 3;
        stsA(b);                                    // A(kt) regs -> smem
        if (kt + 1 < nk) ldgA((kt + 1) * 32);       // prefetch A(kt+1) regs
        if (kt + 1 < nk) asm volatile("cp.async.wait_group 1;" ::: "memory");
        else             asm volatile("cp.async.wait_group 0;" ::: "memory");
        __syncthreads();                            // single barrier per chunk

        const __half* a0 = sm + b * PST;
        const __half* b0 = sm + (3 + b) * PST;
        #pragma unroll
        for (int kk = 0; kk < 32; kk += 16) {
            wmma::fragment<wmma::matrix_a, 16, 16, 16, __half, wmma::row_major> af[2];
            #pragma unroll
            for (int i = 0; i < 2; i++)
                wmma::load_matrix_sync(af[i], a0 + (wm * 32 + i * 16) * PKP + kk, PKP);
            #pragma unroll
            for (int j = 0; j < 4; j++) {
                wmma::fragment<wmma::matrix_b, 16, 16, 16, __half, wmma::col_major> bf;
                wmma::load_matrix_sync(bf, b0 + (wn * 64 + j * 16) * PKP + kk, PKP);
                #pragma unroll
                for (int i = 0; i < 2; i++)
                    wmma::mma_sync(acc[i][j], af[i], bf, acc[i][j]);
            }
        }
        if (kt + 2 < nk) ldB((kt + 2) % 3, (kt + 2) * 32);
    }
    __syncthreads();   // protect smem reuse in epilogue

    float* sC = reinterpret_cast<float*>(sm);
    #pragma unroll
    for (int pass = 0; pass < 2; pass++) {
        if (pass) __syncthreads();
        if ((wm >> 1) == pass) {
            #pragma unroll
            for (int i = 0; i < 2; i++)
                #pragma unroll
                for (int j = 0; j < 4; j++)
                    wmma::store_matrix_sync(sC + ((wm & 1) * 32 + i * 16) * SC_LD + wn * 64 + j * 16,
                                            acc[i][j], SC_LD, wmma::mem_row_major);
        }
        __syncthreads();

        if (TRANS_OUT) {
            #pragma unroll
            for (int cc = 0; cc < 16; cc++) {
                const int c = warp * 16 + cc;
                const float bb = __ldg(bias + n0 + c);
                #pragma unroll
                for (int r0 = 0; r0 < 64; r0 += 32) {
                    float v = sC[(r0 + lane) * SC_LD + c] + bb;
                    C[(size_t)(n0 + c) * ldc + m0 + pass * 64 + r0 + lane] = __float2half(v);
                }
            }
        } else {
            const int r  = tid >> 5;
            const int c4 = (tid & 31) << 2;
            float4 bb = *reinterpret_cast<const float4*>(bias + n0 + c4);
            #pragma unroll
            for (int rr = 0; rr < 64; rr += 8) {
                const int row = r + rr;
                float4 v = *reinterpret_cast<float4*>(&sC[row * SC_LD + c4]);
                __half2 h0 = __floats2half2_rn(v.x + bb.x, v.y + bb.y);
                __half2 h1 = __floats2half2_rn(v.z + bb.z, v.w + bb.w);
                __half2* dst = reinterpret_cast<__half2*>(
                    C + (size_t)(m0 + pass * 64 + row) * ldc + n0 + c4);
                dst[0] = h0; dst[1] = h1;
            }
        }
    }
}

// merged Q+K projection
__global__ __launch_bounds__(256, 2)
void ptgQK(const float* __restrict__ Aq, const float* __restrict__ Ak,
           const __half* __restrict__ Wq, const __half* __restrict__ Wk,
           const float* __restrict__ bias01,
           __half* __restrict__ Cq, __half* __restrict__ Ck)
{
    extern __shared__ __half sm[];
    const int m0 = blockIdx.x * 128;
    const int n0 = blockIdx.y * 128;
    if (blockIdx.z == 0)
        ptg_core<false>(Aq, Wq, bias01,       Cq, DIM, m0, n0, sm);
    else
        ptg_core<false>(Ak, Wk, bias01 + DIM, Ck, DIM, m0, n0, sm);
}

// V projection (transposed output)
__global__ __launch_bounds__(256, 2)
void ptgV(const float* __restrict__ A, const __half* __restrict__ Bm,
          const float* __restrict__ bias, __half* __restrict__ C, int ldc)
{
    extern __shared__ __half sm[];
    ptg_core<true>(A, Bm, bias, C, ldc, blockIdx.x * 128, blockIdx.y * 128, sm);
}

// ---------------- fp16 GEMM (scores-exp, PV): 3-stage, 1 sync/chunk ----------------
template<bool TRI, bool KCAUSAL>
__global__ __launch_bounds__(NTH, 2)
void tg(const __half* __restrict__ A, const __half* __restrict__ Bm,
        void* __restrict__ Cv, const float* __restrict__ rowsum,
        int lda, int ldb, int ldc, int K,
        long strideA, long strideB, long strideC, float scale)
{
    extern __shared__ __half sm[];

    int m0, n0, bz;
    if (TRI) {
        const int r = blockIdx.x;
        int mt = (int)((sqrtf(8.0f * (float)r + 1.0f) - 1.0f) * 0.5f);
        while ((mt + 1) * (mt + 2) / 2 <= r) mt++;
        while (mt * (mt + 1) / 2 > r) mt--;
        const int nt = r - mt * (mt + 1) / 2;
        m0 = mt * BM;
        n0 = nt * BN;
        bz = blockIdx.z;
    } else if (KCAUSAL) {
        const int perM = gridDim.y * gridDim.z;
        const int rank = blockIdx.x + gridDim.x * (blockIdx.y + gridDim.y * blockIdx.z);
        const int mt   = (gridDim.x - 1) - (rank / perM);
        const int rr   = rank % perM;
        m0 = mt * BM;
        n0 = (rr % gridDim.y) * BN;
        bz = rr / gridDim.y;
    } else {
        m0 = blockIdx.x * BM;
        n0 = blockIdx.y * BN;
        bz = blockIdx.z;
    }

    const __half* Ab = A  + (size_t)bz * strideA;
    const __half* Bb = Bm + (size_t)bz * strideB;

    const int kEnd = KCAUSAL ? (m0 + BM) : K;
    const int nk   = kEnd / BKH;

    const int tid  = threadIdx.x;
    const int warp = tid >> 5;
    const int wm   = warp >> 1;
    const int wn   = warp & 1;

    const unsigned smBase = (unsigned)__cvta_generic_to_shared(sm);

    wmma::fragment<wmma::accumulator, 16, 16, 16, float> acc[4][4];
    #pragma unroll
    for (int i = 0; i < 4; i++)
        #pragma unroll
        for (int j = 0; j < 4; j++)
            wmma::fill_fragment(acc[i][j], 0.0f);

    auto loadStage = [&](int st, int k0) {
        const unsigned base = smBase + (unsigned)(st * STAGE_HALVES) * 2u;
        #pragma unroll
        for (int i = 0; i < 8; i++) {
            const int ci = i * NTH + tid;
            const int r = ci >> 3, c8 = (ci & 7) << 3;
            cpa16(base + (unsigned)(r * KP + c8) * 2u,
                  Ab + (size_t)(m0 + r) * lda + k0 + c8);
        }
        const unsigned baseB = base + (unsigned)(BM * KP) * 2u;
        #pragma unroll
        for (int i = 0; i < 8; i++) {
            const int ci = i * NTH + tid;
            const int r = ci >> 3, c8 = (ci & 7) << 3;
            cpa16(baseB + (unsigned)(r * KP + c8) * 2u,
                  Bb + (size_t)(n0 + r) * ldb + k0 + c8);
        }
        asm volatile("cp.async.commit_group;");
    };

    loadStage(0, 0);
    if (nk > 1) loadStage(1, BKH);

    for (int kt = 0; kt < nk; kt++) {
        if (kt + 1 < nk) asm volatile("cp.async.wait_group 1;" ::: "memory");
        else             asm volatile("cp.async.wait_group 0;" ::: "memory");
        __syncthreads();                        // single barrier per chunk

        const __half* a0 = sm + (kt % 3) * STAGE_HALVES;
        const __half* b0 = a0 + BM * KP;

        #pragma unroll
        for (int kk = 0; kk < BKH; kk += 16) {
            wmma::fragment<wmma::matrix_a, 16, 16, 16, __half, wmma::row_major> af[4];
            #pragma unroll
            for (int i = 0; i < 4; i++)
                wmma::load_matrix_sync(af[i], a0 + (wm * 64 + i * 16) * KP + kk, KP);
            #pragma unroll
            for (int j = 0; j < 4; j++) {
                wmma::fragment<wmma::matrix_b, 16, 16, 16, __half, wmma::col_major> bf;
                wmma::load_matrix_sync(bf, b0 + (wn * 64 + j * 16) * KP + kk, KP);
                #pragma unroll
                for (int i = 0; i < 4; i++)
                    wmma::mma_sync(acc[i][j], af[i], bf, acc[i][j]);
            }
        }
        if (kt + 2 < nk) loadStage((kt + 2) % 3, (kt + 2) * BKH);
    }
    __syncthreads();   // protect smem reuse in epilogue

    float* sC = reinterpret_cast<float*>(sm);
    #pragma unroll
    for (int i = 0; i < 4; i++)
        #pragma unroll
        for (int j = 0; j < 4; j++)
            wmma::store_matrix_sync(sC + (wm * 64 + i * 16) * SC_LD + wn * 64 + j * 16,
                                    acc[i][j], SC_LD, wmma::mem_row_major);
    __syncthreads();

    if (TRI) {
        __half* Cb = reinterpret_cast<__half*>(Cv) + (size_t)bz * strideC;
        const int r  = tid >> 5;
        const int c4 = (tid & 31) << 2;
        #pragma unroll
        for (int rr = 0; rr < BM; rr += 4) {
            const int m = m0 + r + rr;
            float4 v = *reinterpret_cast<float4*>(&sC[(r + rr) * SC_LD + c4]);
            const int n = n0 + c4;
            float e0 = (n + 0 <= m) ? __expf(v.x * scale) : 0.0f;
            float e1 = (n + 1 <= m) ? __expf(v.y * scale) : 0.0f;
            float e2 = (n + 2 <= m) ? __expf(v.z * scale) : 0.0f;
            float e3 = (n + 3 <= m) ? __expf(v.w * scale) : 0.0f;
            __half2 h0 = __floats2half2_rn(e0, e1);
            __half2 h1 = __floats2half2_rn(e2, e3);
            __half2* dst = reinterpret_cast<__half2*>(Cb + (size_t)m * ldc + n);
            dst[0] = h0; dst[1] = h1;
        }
    } else {
        const int r  = tid >> 5;
        const int c4 = (tid & 31) << 2;
        float* Cb = reinterpret_cast<float*>(Cv) + (size_t)bz * strideC;
        #pragma unroll
        for (int rr = 0; rr < BM; rr += 4) {
            const int m = m0 + r + rr;
            float4 v = *reinterpret_cast<float4*>(&sC[(r + rr) * SC_LD + c4]);
            float s = KCAUSAL ? (1.0f / __ldg(rowsum + (size_t)bz * SEQ + m)) : scale;
            v.x *= s; v.y *= s; v.z *= s; v.w *= s;
            *reinterpret_cast<float4*>(Cb + (size_t)m * ldc + n0 + c4) = v;
        }
    }
}

// ---------------- row sums of unnormalized probs ----------------
__global__ __launch_bounds__(256)
void rowsum_k(const __half* __restrict__ P, float* __restrict__ RS)
{
    __shared__ float red[8];
    const int row = blockIdx.x;
    const int b   = row >> 11;
    const int i   = row & (SEQ - 1);
    const __half2* p = reinterpret_cast<const __half2*>(P + ((size_t)b * SEQ + i) * SEQ);
    const int len2 = (((i >> 7) + 1) << 7) >> 1;
    const int tid = threadIdx.x, lane = tid & 31, w = tid >> 5;

    float s = 0.f;
    for (int j = tid; j < len2; j += 256) {
        float2 v = __half22float2(p[j]);
        s += v.x + v.y;
    }
    #pragma unroll
    for (int o = 16; o; o >>= 1) s += __shfl_xor_sync(0xffffffffu, s, o);
    if (lane == 0) red[w] = s;
    __syncthreads();
    if (tid == 0) {
        float ss = 0.f;
        #pragma unroll
        for (int x = 0; x < 8; x++) ss += red[x];
        RS[row] = ss;
    }
}

// ---------------- fp32 -> fp16 convert (weights only) ----------------
__global__ __launch_bounds__(256)
void f2h(const float* __restrict__ in, __half* __restrict__ out, int n4)
{
    int i = blockIdx.x * 256 + threadIdx.x;
    if (i < n4) {
        float4 v = reinterpret_cast<const float4*>(in)[i];
        __half2 h0 = __floats2half2_rn(v.x, v.y);
        __half2 h1 = __floats2half2_rn(v.z, v.w);
        reinterpret_cast<__half2*>(out)[2 * i + 0] = h0;
        reinterpret_cast<__half2*>(out)[2 * i + 1] = h1;
    }
}

// bout[e] = b[e] + dot(W[e,:], ctx)
__global__ __launch_bounds__(256)
void bias_prep(const float* __restrict__ W, const float* __restrict__ b,
               const float* __restrict__ ctx, float* __restrict__ bout)
{
    __shared__ float red[8];
    const int e = blockIdx.x;
    const int tid = threadIdx.x, lane = tid & 31, w = tid >> 5;
    float s = 0.f;
    for (int d = tid; d < DIM; d += 256) s += W[(size_t)e * DIM + d] * ctx[d];
    #pragma unroll
    for (int o = 16; o; o >>= 1) s += __shfl_xor_sync(0xffffffffu, s, o);
    if (lane == 0) red[w] = s;
    __syncthreads();
    if (tid == 0) {
        float t = 0.f;
        #pragma unroll
        for (int x = 0; x < 8; x++) t += red[x];
        bout[e] = b[e] + t;
    }
}

extern "C" void kernel_launch(void* const* d_in, const int* in_sizes, int n_in,
                              void* d_out, int out_size)
{
    const float* query = (const float*)d_in[0];
    const float* key   = (const float*)d_in[1];
    const float* value = (const float*)d_in[2];
    const float* ctx   = (const float*)d_in[3];
    const float* Wq    = (const float*)d_in[4];
    const float* bq    = (const float*)d_in[5];
    const float* Wk    = (const float*)d_in[6];
    const float* bk    = (const float*)d_in[7];
    const float* Wv    = (const float*)d_in[8];
    const float* bv    = (const float*)d_in[9];
    float* out = (float*)d_out;

    float *pRS, *pBias;
    __half *phP, *phQ, *phK, *phVt, *phWq, *phWk, *phWv;
    cudaGetSymbolAddress((void**)&pRS,  g_RS);
    cudaGetSymbolAddress((void**)&phP,  g_hP);
    cudaGetSymbolAddress((void**)&phQ,  g_hQ);
    cudaGetSymbolAddress((void**)&phK,  g_hK);
    cudaGetSymbolAddress((void**)&phVt, g_hVt);
    cudaGetSymbolAddress((void**)&phWq, g_hWq);
    cudaGetSymbolAddress((void**)&phWk, g_hWk);
    cudaGetSymbolAddress((void**)&phWv, g_hWv);
    cudaGetSymbolAddress((void**)&pBias, g_bias);

    cudaFuncSetAttribute(tg<true,  false>, cudaFuncAttributeMaxDynamicSharedMemorySize, SMEM_BYTES);
    cudaFuncSetAttribute(tg<false, true >, cudaFuncAttributeMaxDynamicSharedMemorySize, SMEM_BYTES);
    cudaFuncSetAttribute(ptgQK, cudaFuncAttributeMaxDynamicSharedMemorySize, PSMEM_BYTES);
    cudaFuncSetAttribute(ptgV,  cudaFuncAttributeMaxDynamicSharedMemorySize, PSMEM_BYTES);

    const int nW4 = DIM * DIM / 4;

    // ---- fork aux stream (V projection overlaps scores+rowsum) ----
    cudaStream_t s1 = 0;
    cudaEvent_t evFork = 0, evQK = 0, evJoin = 0;
    bool forked = false;
    if (cudaStreamCreateWithFlags(&s1, cudaStreamNonBlocking) == cudaSuccess) {
        cudaEventCreateWithFlags(&evFork, cudaEventDisableTiming);
        cudaEventCreateWithFlags(&evQK,   cudaEventDisableTiming);
        cudaEventCreateWithFlags(&evJoin, cudaEventDisableTiming);
        forked = (cudaEventRecord(evFork, 0) == cudaSuccess) &&
                 (cudaStreamWaitEvent(s1, evFork, 0) == cudaSuccess);
    }
    cudaStream_t sAux = forked ? s1 : 0;

    // prelude (R12 layout)
    bias_prep<<<DIM, 256>>>(Wq, bq, ctx, pBias);
    bias_prep<<<DIM, 256>>>(Wk, bk, ctx, pBias + DIM);
    f2h<<<nW4 / 256, 256>>>(Wq, phWq, nW4);
    f2h<<<nW4 / 256, 256>>>(Wk, phWk, nW4);
    f2h<<<nW4 / 256, 256, 0, sAux>>>(Wv, phWv, nW4);

    // merged Q+K projection
    dim3 gp2(MTOT / 128, DIM / 128, 2);
    ptgQK<<<gp2, 256, PSMEM_BYTES>>>(query, key, phWq, phWk, pBias, phQ, phK);

    if (forked) { cudaEventRecord(evQK, 0); cudaStreamWaitEvent(sAux, evQK, 0); }
    // V projection (aux) -> transposed fp16 Vt, overlaps scores+rowsum
    dim3 gpv(MTOT / 128, DIM / 128, 1);
    ptgV<<<gpv, 256, PSMEM_BYTES, sAux>>>(value, phWv, bv, phVt, MTOT);
    if (forked) cudaEventRecord(evJoin, sAux);

    // P' = exp(Q@K^T * scale) fp16, causal-masked — triangular grid
    dim3 gs(NTRI, 1, BATCH);
    tg<true, false><<<gs, NTH, SMEM_BYTES>>>(phQ, phK, phP, nullptr,
        DIM, DIM, SEQ, DIM,
        (long)SEQ * DIM, (long)SEQ * DIM, (long)SEQ * SEQ, 0.03125f);

    // row sums of P'
    rowsum_k<<<MTOT, 256>>>(phP, pRS);

    if (forked) cudaStreamWaitEvent(0, evJoin, 0);

    // out = (P' @ Vt^T) / rowsum  (K limited by causality; LPT remap)
    dim3 gv(SEQ / 128, DIM / 128, BATCH);
    tg<false, true><<<gv, NTH, SMEM_BYTES>>>(phP, phVt, out, pRS,
        SEQ, MTOT, DIM, SEQ,
        (long)SEQ * SEQ, (long)SEQ, (long)SEQ * DIM, 1.0f);

    if (forked) {
        cudaEventDestroy(evFork);
        cudaEventDestroy(evQK);
        cudaEventDestroy(evJoin);
    }
    if (s1) cudaStreamDestroy(s1);
}